// round 15
// baseline (speedup 1.0000x reference)
#include <cuda_runtime.h>
#include <cuda_fp16.h>

#define NN 100000
#define EE 1600000
#define HH 64
#define GG 128
#define CC 10
#define NB1 98   // ceil(NN/1024)

typedef unsigned long long ull;

// ---------------- scratch (device globals: no runtime allocation) ----------------
__device__ int     g_csrc[EE];
__device__ int     g_deg[NN];
__device__ int     g_rowptr[NN];
__device__ int     g_cursor[NN];
__device__ int     g_incl[NN];
__device__ int     g_bsum[128];
__device__ __half2 g_h1h[(size_t)NN * 32];   // fp16 pre-activation features (both layers)
__device__ float   g_hx[(size_t)NN * HH];    // post softmax+bias+elu (fp32, both layers)
__device__ float   g_als[NN];
__device__ float   g_ald[NN];
__device__ int     g_i64;

__device__ __forceinline__ float lrelu(float x) { return x > 0.f ? x : 0.2f * x; }
__device__ __forceinline__ float elu_(float x)  { return x > 0.f ? x : expm1f(x); }

// ---- packed fp32x2 helpers (Blackwell FFMA2; bit-identical fp32 per lane) ----
__device__ __forceinline__ ull pack2(float lo, float hi) {
    ull r;
    asm("mov.b64 %0, {%1, %2};" : "=l"(r) : "f"(lo), "f"(hi));
    return r;
}
__device__ __forceinline__ void unpack2(ull v, float& lo, float& hi) {
    asm("mov.b64 {%0, %1}, %2;" : "=f"(lo), "=f"(hi) : "l"(v));
}
__device__ __forceinline__ ull fma2(ull a, ull b, ull c) {
    ull d;
    asm("fma.rn.f32x2 %0, %1, %2, %3;" : "=l"(d) : "l"(a), "l"(b), "l"(c));
    return d;
}

// ---------------- zero + dtype detect (int64 indices have zero high words) ----------
__global__ void zero_kernel(const int* __restrict__ ei_w, float* __restrict__ out) {
    int i = blockIdx.x * blockDim.x + threadIdx.x;
    if (i == 0) {
        int flag = 1;
        for (int k = 0; k < 64; k++)
            if (ei_w[2 * k + 1] != 0) flag = 0;
        g_i64 = flag;
    }
    if (i < NN) g_deg[i] = 0;
    if (i < GG * CC) out[i] = 0.f;
}

__global__ void prep_kernel(const int* __restrict__ ei_w) {
    int i = blockIdx.x * blockDim.x + threadIdx.x;
    if (i >= EE) return;
    int d;
    if (g_i64) d = (int)((const long long*)ei_w)[EE + i];
    else       d = ei_w[EE + i];
    atomicAdd(&g_deg[d], 1);
}

__global__ void scan1_kernel() {
    __shared__ int sm[1024];
    int t = threadIdx.x;
    int i = blockIdx.x * 1024 + t;
    int v = (i < NN) ? g_deg[i] : 0;
    sm[t] = v;
    __syncthreads();
#pragma unroll
    for (int off = 1; off < 1024; off <<= 1) {
        int x = (t >= off) ? sm[t - off] : 0;
        __syncthreads();
        sm[t] += x;
        __syncthreads();
    }
    if (i < NN) g_incl[i] = sm[t];
    if (t == 1023) g_bsum[blockIdx.x] = sm[t];
}

// scan3 with the (tiny) block-sum scan inlined
__global__ void scan3_kernel() {
    __shared__ int sb[128];
    int t = threadIdx.x;
    if (t < 128) sb[t] = (t < NB1) ? g_bsum[t] : 0;
    __syncthreads();
#pragma unroll
    for (int off = 1; off < 128; off <<= 1) {
        int x = 0;
        if (t < 128 && t >= off) x = sb[t - off];
        __syncthreads();
        if (t < 128) sb[t] += x;
        __syncthreads();
    }
    int i = blockIdx.x * blockDim.x + t;
    if (i >= NN) return;
    int b = i >> 10;
    int bexcl = (b == 0) ? 0 : sb[b - 1];
    int excl = g_incl[i] - g_deg[i] + bexcl;
    g_rowptr[i] = excl;
    g_cursor[i] = excl;
}

__global__ void fill_kernel(const int* __restrict__ ei_w) {
    int i = blockIdx.x * blockDim.x + threadIdx.x;
    if (i >= EE) return;
    int s, d;
    if (g_i64) {
        const long long* e64 = (const long long*)ei_w;
        s = (int)e64[i];
        d = (int)e64[EE + i];
    } else {
        s = ei_w[i];
        d = ei_w[EE + i];
    }
    int slot = atomicAdd(&g_cursor[d], 1);
    g_csrc[slot] = s;
}

// ---------------- GEMM (Nx64 @ 64x64): smem-staged x + packed f32x2 FMA ------------
// mode 0: read external x; mode 1: read g_hx
// Block stages its 128-row x tile into padded smem with fully coalesced bulk loads,
// so the K-loop reads x via low-latency LDS instead of 32-line-divergent LDG.
__global__ __launch_bounds__(128) void gemm_gat(
    int mode, const float* __restrict__ xext, const float* __restrict__ W,
    const float* __restrict__ avs, const float* __restrict__ avd)
{
    __shared__ __align__(16) float4 Ws[64 * 16];     // 16 KB weights
    __shared__ __align__(16) float  xs[128 * 68];    // 34 KB padded x tile
    __shared__ float as_s[64], ad_s[64];
    int tid = threadIdx.x;
    const float4* W4 = (const float4*)W;
    for (int i = tid; i < 64 * 16; i += 128) Ws[i] = W4[i];
    if (tid < 64) { as_s[tid] = avs[tid]; ad_s[tid] = avd[tid]; }

    // stage x tile: idx runs over 128 rows x 16 float4s; consecutive lanes ->
    // consecutive global float4s -> fully coalesced 128B transactions.
    int row0 = blockIdx.x * 128;
    const float* xin = mode ? g_hx : xext;
    const float4* xg = (const float4*)(xin + (size_t)row0 * HH);
    int nrows = NN - row0; if (nrows > 128) nrows = 128;
#pragma unroll
    for (int it = 0; it < 16; it++) {
        int idx = it * 128 + tid;
        int r = idx >> 4, c = idx & 15;
        float4 v = make_float4(0.f, 0.f, 0.f, 0.f);
        if (r < nrows) v = xg[idx];
        *(float4*)&xs[r * 68 + 4 * c] = v;
    }
    __syncthreads();

    int row = row0 + tid;
    if (row >= NN) return;

    ull o2[32];
#pragma unroll
    for (int c = 0; c < 32; c++) o2[c] = 0ull;

    const float* xrow = xs + tid * 68;
    const ulonglong2* Ws2 = (const ulonglong2*)Ws;
#pragma unroll 4
    for (int k4 = 0; k4 < 16; k4++) {
        float4 v = *(const float4*)&xrow[4 * k4];
        float xk[4] = {v.x, v.y, v.z, v.w};
#pragma unroll
        for (int kk = 0; kk < 4; kk++) {
            int k = 4 * k4 + kk;
            ull xv2 = pack2(xk[kk], xk[kk]);
#pragma unroll
            for (int c4 = 0; c4 < 16; c4++) {
                ulonglong2 w = Ws2[k * 16 + c4];
                o2[2 * c4 + 0] = fma2(w.x, xv2, o2[2 * c4 + 0]);
                o2[2 * c4 + 1] = fma2(w.y, xv2, o2[2 * c4 + 1]);
            }
        }
    }

    // epilogue: fp32 attention halves, fp16 h row
    float als = 0.f, ald = 0.f;
    __half2 hrow[32];
#pragma unroll
    for (int c2 = 0; c2 < 32; c2++) {
        float a, b;
        unpack2(o2[c2], a, b);
        hrow[c2] = __floats2half2_rn(a, b);
        als += a * as_s[2 * c2] + b * as_s[2 * c2 + 1];
        ald += a * ad_s[2 * c2] + b * ad_s[2 * c2 + 1];
    }
    float4* dst = (float4*)(g_h1h + (size_t)row * 32);
    const float4* srcv = (const float4*)hrow;
#pragma unroll
    for (int i = 0; i < 8; i++) dst[i] = srcv[i];

    g_als[row] = als;
    g_ald[row] = ald;
}

// ---------------- warp-per-dst gather: softmax + weighted sum + bias + elu ----------
__global__ __launch_bounds__(256) void gather_kernel(const float* __restrict__ bias) {
    __shared__ float bs[64];
    if (threadIdx.x < 64) bs[threadIdx.x] = bias[threadIdx.x];
    __syncthreads();

    int d = (blockIdx.x * 256 + threadIdx.x) >> 5;
    int lane = threadIdx.x & 31;
    if (d >= NN) return;

    const __half2* __restrict__ h = g_h1h;
    const unsigned FULL = 0xffffffffu;
    float aldd = g_ald[d];
    float m_self = lrelu(g_als[d] + aldd);
    int row = g_rowptr[d];
    int deg = g_deg[d];

    float2 hv0 = __half22float2(h[(size_t)d * 32 + lane]);
    float accx, accy, den, exs;

    if (deg <= 32) {
        int   s_l = 0;
        float e_l = -1e30f;
        if (lane < deg) {
            s_l = g_csrc[row + lane];
            e_l = lrelu(g_als[s_l] + aldd);
        }
        float m = fmaxf(m_self, e_l);
#pragma unroll
        for (int off = 16; off; off >>= 1) m = fmaxf(m, __shfl_xor_sync(FULL, m, off));
        float ex_l = (lane < deg) ? __expf(e_l - m) : 0.f;
        den = ex_l;
        exs = __expf(m_self - m);
        accx = exs * hv0.x;
        accy = exs * hv0.y;
        int k = 0;
        for (; k + 4 <= deg; k += 4) {
            int   s0 = __shfl_sync(FULL, s_l, k + 0);
            int   s1 = __shfl_sync(FULL, s_l, k + 1);
            int   s2 = __shfl_sync(FULL, s_l, k + 2);
            int   s3 = __shfl_sync(FULL, s_l, k + 3);
            float x0 = __shfl_sync(FULL, ex_l, k + 0);
            float x1 = __shfl_sync(FULL, ex_l, k + 1);
            float x2 = __shfl_sync(FULL, ex_l, k + 2);
            float x3 = __shfl_sync(FULL, ex_l, k + 3);
            float2 v0 = __half22float2(h[(size_t)s0 * 32 + lane]);
            float2 v1 = __half22float2(h[(size_t)s1 * 32 + lane]);
            float2 v2 = __half22float2(h[(size_t)s2 * 32 + lane]);
            float2 v3 = __half22float2(h[(size_t)s3 * 32 + lane]);
            accx = fmaf(x0, v0.x, accx); accy = fmaf(x0, v0.y, accy);
            accx = fmaf(x1, v1.x, accx); accy = fmaf(x1, v1.y, accy);
            accx = fmaf(x2, v2.x, accx); accy = fmaf(x2, v2.y, accy);
            accx = fmaf(x3, v3.x, accx); accy = fmaf(x3, v3.y, accy);
        }
        for (; k < deg; k++) {
            float ex = __shfl_sync(FULL, ex_l, k);
            int   s  = __shfl_sync(FULL, s_l, k);
            float2 hv = __half22float2(h[(size_t)s * 32 + lane]);
            accx = fmaf(ex, hv.x, accx);
            accy = fmaf(ex, hv.y, accy);
        }
    } else {
        float m = m_self;
        for (int j = lane; j < deg; j += 32) {
            int s = g_csrc[row + j];
            m = fmaxf(m, lrelu(g_als[s] + aldd));
        }
#pragma unroll
        for (int off = 16; off; off >>= 1) m = fmaxf(m, __shfl_xor_sync(FULL, m, off));
        exs = __expf(m_self - m);
        accx = exs * hv0.x;
        accy = exs * hv0.y;
        den = 0.f;
        for (int base = 0; base < deg; base += 32) {
            int jl = base + lane;
            int s_l = 0; float ex_l = 0.f;
            if (jl < deg) {
                s_l = g_csrc[row + jl];
                ex_l = __expf(lrelu(g_als[s_l] + aldd) - m);
            }
            den += ex_l;
            int cnt = deg - base; if (cnt > 32) cnt = 32;
            int k = 0;
            for (; k + 4 <= cnt; k += 4) {
                int   s0 = __shfl_sync(FULL, s_l, k + 0);
                int   s1 = __shfl_sync(FULL, s_l, k + 1);
                int   s2 = __shfl_sync(FULL, s_l, k + 2);
                int   s3 = __shfl_sync(FULL, s_l, k + 3);
                float x0 = __shfl_sync(FULL, ex_l, k + 0);
                float x1 = __shfl_sync(FULL, ex_l, k + 1);
                float x2 = __shfl_sync(FULL, ex_l, k + 2);
                float x3 = __shfl_sync(FULL, ex_l, k + 3);
                float2 v0 = __half22float2(h[(size_t)s0 * 32 + lane]);
                float2 v1 = __half22float2(h[(size_t)s1 * 32 + lane]);
                float2 v2 = __half22float2(h[(size_t)s2 * 32 + lane]);
                float2 v3 = __half22float2(h[(size_t)s3 * 32 + lane]);
                accx = fmaf(x0, v0.x, accx); accy = fmaf(x0, v0.y, accy);
                accx = fmaf(x1, v1.x, accx); accy = fmaf(x1, v1.y, accy);
                accx = fmaf(x2, v2.x, accx); accy = fmaf(x2, v2.y, accy);
                accx = fmaf(x3, v3.x, accx); accy = fmaf(x3, v3.y, accy);
            }
            for (; k < cnt; k++) {
                float ex = __shfl_sync(FULL, ex_l, k);
                int   s  = __shfl_sync(FULL, s_l, k);
                float2 hv = __half22float2(h[(size_t)s * 32 + lane]);
                accx = fmaf(ex, hv.x, accx);
                accy = fmaf(ex, hv.y, accy);
            }
        }
    }
#pragma unroll
    for (int off = 16; off; off >>= 1) den += __shfl_xor_sync(FULL, den, off);
    den += exs;   // self-loop term (warp-uniform)
    float inv = 1.f / den;
    float2 o;
    o.x = elu_(accx * inv + bs[2 * lane + 0]);
    o.y = elu_(accy * inv + bs[2 * lane + 1]);
    *(float2*)(g_hx + (size_t)d * HH + 2 * lane) = o;
}

// ---------------- MLP head + pooled output, packed f32x2 FMA ----------------
__global__ __launch_bounds__(128) void final_kernel(
    const float* __restrict__ mw1, const float* __restrict__ mb1,
    const float* __restrict__ mw2, const float* __restrict__ mb2,
    const void* __restrict__ batch, float* __restrict__ out)
{
    __shared__ __align__(16) float mw1T[64 * 64];   // transposed: [j*64 + c]
    __shared__ __align__(16) float mw2s[64 * CC];
    __shared__ float mb1s[64], mb2s[CC];
    int tid = threadIdx.x;
    for (int i = tid; i < 64 * 64; i += 128) {
        int c = i >> 6, j = i & 63;
        mw1T[j * 64 + c] = mw1[i];
    }
    for (int i = tid; i < 64 * CC; i += 128) mw2s[i] = mw2[i];
    if (tid < 64) mb1s[tid] = mb1[tid];
    if (tid < CC) mb2s[tid] = mb2[tid];
    __syncthreads();

    int row = blockIdx.x * 128 + tid;
    int lane = tid & 31;
    bool active = row < NN;

    float o[CC];
#pragma unroll
    for (int c = 0; c < CC; c++) o[c] = 0.f;
    int g = 0;

    if (active) {
        size_t base = (size_t)row * HH;
        ull hf2[32];
        const ulonglong2* hp2 = (const ulonglong2*)(g_hx + base);
#pragma unroll
        for (int i = 0; i < 16; i++) {
            ulonglong2 p = hp2[i];
            hf2[2 * i + 0] = p.x;
            hf2[2 * i + 1] = p.y;
        }
        ull oc2[CC / 2];
#pragma unroll
        for (int c2 = 0; c2 < CC / 2; c2++) oc2[c2] = pack2(mb2s[2 * c2], mb2s[2 * c2 + 1]);

        const ulonglong2* m1 = (const ulonglong2*)mw1T;
#pragma unroll 4
        for (int j = 0; j < 64; j++) {
            ull t2 = pack2(mb1s[j], 0.f);
#pragma unroll
            for (int c4 = 0; c4 < 16; c4++) {
                ulonglong2 w = m1[j * 16 + c4];
                t2 = fma2(hf2[2 * c4 + 0], w.x, t2);
                t2 = fma2(hf2[2 * c4 + 1], w.y, t2);
            }
            float tlo, thi;
            unpack2(t2, tlo, thi);
            float t = fmaxf(tlo + thi, 0.f);
            ull tt = pack2(t, t);
            const ull* w2 = (const ull*)(mw2s + j * CC);
#pragma unroll
            for (int c2 = 0; c2 < CC / 2; c2++) oc2[c2] = fma2(tt, w2[c2], oc2[c2]);
        }
#pragma unroll
        for (int c2 = 0; c2 < CC / 2; c2++) unpack2(oc2[c2], o[2 * c2], o[2 * c2 + 1]);

        if (g_i64) g = (int)((const long long*)batch)[row];
        else       g = ((const int*)batch)[row];
    }

    unsigned mask = 0xffffffffu;
    int g0 = __shfl_sync(mask, g, 0);
    bool uni = __all_sync(mask, g == g0);
    if (uni) {
#pragma unroll
        for (int c = 0; c < CC; c++) {
            float v = o[c];
#pragma unroll
            for (int off = 16; off > 0; off >>= 1) v += __shfl_xor_sync(mask, v, off);
            if (lane == 0) atomicAdd(&out[g0 * CC + c], v);
        }
    } else {
        if (active) {
#pragma unroll
            for (int c = 0; c < CC; c++) atomicAdd(&out[g * CC + c], o[c]);
        }
    }
}

// ---------------- launch (single stream, 10 launches) ----------------
extern "C" void kernel_launch(void* const* d_in, const int* in_sizes, int n_in,
                              void* d_out, int out_size) {
    const float* x     = (const float*)d_in[0];
    const int*   ei_w  = (const int*)d_in[1];
    const void*  batch = d_in[2];
    const float* W1  = (const float*)d_in[3];
    const float* as1 = (const float*)d_in[4];
    const float* ad1 = (const float*)d_in[5];
    const float* b1  = (const float*)d_in[6];
    const float* W2  = (const float*)d_in[7];
    const float* as2 = (const float*)d_in[8];
    const float* ad2 = (const float*)d_in[9];
    const float* b2  = (const float*)d_in[10];
    const float* mw1 = (const float*)d_in[11];
    const float* mb1 = (const float*)d_in[12];
    const float* mw2 = (const float*)d_in[13];
    const float* mb2 = (const float*)d_in[14];
    float* out = (float*)d_out;

    int gb = (NN + 127) / 128;
    int nb = (NN + 255) / 256;
    int eb = (EE + 255) / 256;
    int wb = ((NN * 32) + 255) / 256;

    zero_kernel<<<nb, 256>>>(ei_w, out);
    prep_kernel<<<eb, 256>>>(ei_w);
    scan1_kernel<<<NB1, 1024>>>();
    scan3_kernel<<<nb, 256>>>();
    fill_kernel<<<eb, 256>>>(ei_w);

    gemm_gat<<<gb, 128>>>(0, x, W1, as1, ad1);
    gather_kernel<<<wb, 256>>>(b1);

    gemm_gat<<<gb, 128>>>(1, x, W2, as2, ad2);
    gather_kernel<<<wb, 256>>>(b2);

    final_kernel<<<gb, 128>>>(mw1, mb1, mw2, mb2, batch, out);
}

// round 16
// speedup vs baseline: 1.4397x; 1.4397x over previous
#include <cuda_runtime.h>
#include <cuda_fp16.h>

#define NN 100000
#define EE 1600000
#define HH 64
#define GG 128
#define CC 10
#define NB1 98   // ceil(NN/1024)

typedef unsigned long long ull;

// ---------------- scratch (device globals: no runtime allocation) ----------------
__device__ int     g_csrc[EE];
__device__ int     g_deg[NN];
__device__ int     g_rowptr[NN];
__device__ int     g_cursor[NN];
__device__ int     g_incl[NN];
__device__ int     g_bsum[128];
__device__ __half2 g_h1h[(size_t)NN * 32];   // fp16 pre-activation features (both layers)
__device__ float   g_hx[(size_t)NN * HH];    // post softmax+bias+elu (fp32, both layers)
__device__ float   g_als[NN];
__device__ float   g_ald[NN];
__device__ int     g_i64;

__device__ __forceinline__ float lrelu(float x) { return x > 0.f ? x : 0.2f * x; }
__device__ __forceinline__ float elu_(float x)  { return x > 0.f ? x : expm1f(x); }

// ---- packed fp32x2 helpers (Blackwell FFMA2; bit-identical fp32 per lane) ----
__device__ __forceinline__ ull pack2(float lo, float hi) {
    ull r;
    asm("mov.b64 %0, {%1, %2};" : "=l"(r) : "f"(lo), "f"(hi));
    return r;
}
__device__ __forceinline__ void unpack2(ull v, float& lo, float& hi) {
    asm("mov.b64 {%0, %1}, %2;" : "=f"(lo), "=f"(hi) : "l"(v));
}
__device__ __forceinline__ ull fma2(ull a, ull b, ull c) {
    ull d;
    asm("fma.rn.f32x2 %0, %1, %2, %3;" : "=l"(d) : "l"(a), "l"(b), "l"(c));
    return d;
}

// ---------------- zero + dtype detect (int64 indices have zero high words) ----------
__global__ void zero_kernel(const int* __restrict__ ei_w, float* __restrict__ out) {
    int i = blockIdx.x * blockDim.x + threadIdx.x;
    if (i == 0) {
        int flag = 1;
        for (int k = 0; k < 64; k++)
            if (ei_w[2 * k + 1] != 0) flag = 0;
        g_i64 = flag;
    }
    if (i < NN) g_deg[i] = 0;
    if (i < GG * CC) out[i] = 0.f;
}

__global__ void prep_kernel(const int* __restrict__ ei_w) {
    int i = blockIdx.x * blockDim.x + threadIdx.x;
    if (i >= EE) return;
    int d;
    if (g_i64) d = (int)((const long long*)ei_w)[EE + i];
    else       d = ei_w[EE + i];
    atomicAdd(&g_deg[d], 1);
}

__global__ void scan1_kernel() {
    __shared__ int sm[1024];
    int t = threadIdx.x;
    int i = blockIdx.x * 1024 + t;
    int v = (i < NN) ? g_deg[i] : 0;
    sm[t] = v;
    __syncthreads();
#pragma unroll
    for (int off = 1; off < 1024; off <<= 1) {
        int x = (t >= off) ? sm[t - off] : 0;
        __syncthreads();
        sm[t] += x;
        __syncthreads();
    }
    if (i < NN) g_incl[i] = sm[t];
    if (t == 1023) g_bsum[blockIdx.x] = sm[t];
}

// scan3 with the (tiny) block-sum scan inlined
__global__ void scan3_kernel() {
    __shared__ int sb[128];
    int t = threadIdx.x;
    if (t < 128) sb[t] = (t < NB1) ? g_bsum[t] : 0;
    __syncthreads();
#pragma unroll
    for (int off = 1; off < 128; off <<= 1) {
        int x = 0;
        if (t < 128 && t >= off) x = sb[t - off];
        __syncthreads();
        if (t < 128) sb[t] += x;
        __syncthreads();
    }
    int i = blockIdx.x * blockDim.x + t;
    if (i >= NN) return;
    int b = i >> 10;
    int bexcl = (b == 0) ? 0 : sb[b - 1];
    int excl = g_incl[i] - g_deg[i] + bexcl;
    g_rowptr[i] = excl;
    g_cursor[i] = excl;
}

__global__ void fill_kernel(const int* __restrict__ ei_w) {
    int i = blockIdx.x * blockDim.x + threadIdx.x;
    if (i >= EE) return;
    int s, d;
    if (g_i64) {
        const long long* e64 = (const long long*)ei_w;
        s = (int)e64[i];
        d = (int)e64[EE + i];
    } else {
        s = ei_w[i];
        d = ei_w[EE + i];
    }
    int slot = atomicAdd(&g_cursor[d], 1);
    g_csrc[slot] = s;
}

// ---------------- GEMM (Nx64 @ 64x64): 2 threads per row (32 cols each) -------------
// mode 0: read external x; mode 1: read g_hx.
// 256 threads = 128 rows x 2 halves. Each thread: 16 ull accumulators (~70 regs)
// -> ~2.4x the warps of the monolithic version to hide x-row LDG latency.
// K-loop structure per thread is unchanged (single pass, register accumulators).
__global__ __launch_bounds__(256) void gemm_gat(
    int mode, const float* __restrict__ xext, const float* __restrict__ W,
    const float* __restrict__ avs, const float* __restrict__ avd)
{
    __shared__ __align__(16) float4 Ws[64 * 16];
    __shared__ float as_s[64], ad_s[64];
    __shared__ float pals[256], pald[256];
    int tid = threadIdx.x;
    const float4* W4 = (const float4*)W;
    for (int i = tid; i < 64 * 16; i += 256) Ws[i] = W4[i];
    if (tid < 64) { as_s[tid] = avs[tid]; ad_s[tid] = avd[tid]; }
    __syncthreads();

    int half = tid >> 7;          // 0: cols 0..31, 1: cols 32..63
    int rid  = tid & 127;
    int row  = blockIdx.x * 128 + rid;
    bool active = row < NN;

    float als_p = 0.f, ald_p = 0.f;

    if (active) {
        size_t base = (size_t)row * HH;
        const float* xin = mode ? g_hx : xext;
        const float4* xp = (const float4*)(xin + base);
        const ulonglong2* Ws2 = (const ulonglong2*)Ws;

        ull o2[16];
#pragma unroll
        for (int c = 0; c < 16; c++) o2[c] = 0ull;

#pragma unroll 4
        for (int k4 = 0; k4 < 16; k4++) {
            float4 v = xp[k4];     // partner thread's read of the same line: L1 hit
            float xk[4] = {v.x, v.y, v.z, v.w};
#pragma unroll
            for (int kk = 0; kk < 4; kk++) {
                int k = 4 * k4 + kk;
                ull xv2 = pack2(xk[kk], xk[kk]);
                const ulonglong2* wrow = Ws2 + k * 16 + half * 8;  // warp-uniform -> broadcast
#pragma unroll
                for (int c4 = 0; c4 < 8; c4++) {
                    ulonglong2 w = wrow[c4];
                    o2[2 * c4 + 0] = fma2(w.x, xv2, o2[2 * c4 + 0]);
                    o2[2 * c4 + 1] = fma2(w.y, xv2, o2[2 * c4 + 1]);
                }
            }
        }

        // epilogue: this thread's 32 columns -> fp16 store + attention partials
        __half2 hrow[16];
#pragma unroll
        for (int c2 = 0; c2 < 16; c2++) {
            float a, b;
            unpack2(o2[c2], a, b);
            hrow[c2] = __floats2half2_rn(a, b);
            int col = half * 32 + 2 * c2;
            als_p += a * as_s[col] + b * as_s[col + 1];
            ald_p += a * ad_s[col] + b * ad_s[col + 1];
        }
        float4* dst = (float4*)(g_h1h + (size_t)row * 32 + half * 16);
        const float4* srcv = (const float4*)hrow;
#pragma unroll
        for (int i = 0; i < 4; i++) dst[i] = srcv[i];
    }

    pals[tid] = als_p;
    pald[tid] = ald_p;
    __syncthreads();

    if (half == 0 && active) {
        g_als[row] = pals[tid] + pals[tid + 128];
        g_ald[row] = pald[tid] + pald[tid + 128];
    }
}

// ---------------- warp-per-dst gather: softmax + weighted sum + bias + elu ----------
__global__ __launch_bounds__(256) void gather_kernel(const float* __restrict__ bias) {
    __shared__ float bs[64];
    if (threadIdx.x < 64) bs[threadIdx.x] = bias[threadIdx.x];
    __syncthreads();

    int d = (blockIdx.x * 256 + threadIdx.x) >> 5;
    int lane = threadIdx.x & 31;
    if (d >= NN) return;

    const __half2* __restrict__ h = g_h1h;
    const unsigned FULL = 0xffffffffu;
    float aldd = g_ald[d];
    float m_self = lrelu(g_als[d] + aldd);
    int row = g_rowptr[d];
    int deg = g_deg[d];

    float2 hv0 = __half22float2(h[(size_t)d * 32 + lane]);
    float accx, accy, den, exs;

    if (deg <= 32) {
        int   s_l = 0;
        float e_l = -1e30f;
        if (lane < deg) {
            s_l = g_csrc[row + lane];
            e_l = lrelu(g_als[s_l] + aldd);
        }
        float m = fmaxf(m_self, e_l);
#pragma unroll
        for (int off = 16; off; off >>= 1) m = fmaxf(m, __shfl_xor_sync(FULL, m, off));
        float ex_l = (lane < deg) ? __expf(e_l - m) : 0.f;
        den = ex_l;
        exs = __expf(m_self - m);
        accx = exs * hv0.x;
        accy = exs * hv0.y;
        int k = 0;
        for (; k + 4 <= deg; k += 4) {
            int   s0 = __shfl_sync(FULL, s_l, k + 0);
            int   s1 = __shfl_sync(FULL, s_l, k + 1);
            int   s2 = __shfl_sync(FULL, s_l, k + 2);
            int   s3 = __shfl_sync(FULL, s_l, k + 3);
            float x0 = __shfl_sync(FULL, ex_l, k + 0);
            float x1 = __shfl_sync(FULL, ex_l, k + 1);
            float x2 = __shfl_sync(FULL, ex_l, k + 2);
            float x3 = __shfl_sync(FULL, ex_l, k + 3);
            float2 v0 = __half22float2(h[(size_t)s0 * 32 + lane]);
            float2 v1 = __half22float2(h[(size_t)s1 * 32 + lane]);
            float2 v2 = __half22float2(h[(size_t)s2 * 32 + lane]);
            float2 v3 = __half22float2(h[(size_t)s3 * 32 + lane]);
            accx = fmaf(x0, v0.x, accx); accy = fmaf(x0, v0.y, accy);
            accx = fmaf(x1, v1.x, accx); accy = fmaf(x1, v1.y, accy);
            accx = fmaf(x2, v2.x, accx); accy = fmaf(x2, v2.y, accy);
            accx = fmaf(x3, v3.x, accx); accy = fmaf(x3, v3.y, accy);
        }
        for (; k < deg; k++) {
            float ex = __shfl_sync(FULL, ex_l, k);
            int   s  = __shfl_sync(FULL, s_l, k);
            float2 hv = __half22float2(h[(size_t)s * 32 + lane]);
            accx = fmaf(ex, hv.x, accx);
            accy = fmaf(ex, hv.y, accy);
        }
    } else {
        float m = m_self;
        for (int j = lane; j < deg; j += 32) {
            int s = g_csrc[row + j];
            m = fmaxf(m, lrelu(g_als[s] + aldd));
        }
#pragma unroll
        for (int off = 16; off; off >>= 1) m = fmaxf(m, __shfl_xor_sync(FULL, m, off));
        exs = __expf(m_self - m);
        accx = exs * hv0.x;
        accy = exs * hv0.y;
        den = 0.f;
        for (int base = 0; base < deg; base += 32) {
            int jl = base + lane;
            int s_l = 0; float ex_l = 0.f;
            if (jl < deg) {
                s_l = g_csrc[row + jl];
                ex_l = __expf(lrelu(g_als[s_l] + aldd) - m);
            }
            den += ex_l;
            int cnt = deg - base; if (cnt > 32) cnt = 32;
            int k = 0;
            for (; k + 4 <= cnt; k += 4) {
                int   s0 = __shfl_sync(FULL, s_l, k + 0);
                int   s1 = __shfl_sync(FULL, s_l, k + 1);
                int   s2 = __shfl_sync(FULL, s_l, k + 2);
                int   s3 = __shfl_sync(FULL, s_l, k + 3);
                float x0 = __shfl_sync(FULL, ex_l, k + 0);
                float x1 = __shfl_sync(FULL, ex_l, k + 1);
                float x2 = __shfl_sync(FULL, ex_l, k + 2);
                float x3 = __shfl_sync(FULL, ex_l, k + 3);
                float2 v0 = __half22float2(h[(size_t)s0 * 32 + lane]);
                float2 v1 = __half22float2(h[(size_t)s1 * 32 + lane]);
                float2 v2 = __half22float2(h[(size_t)s2 * 32 + lane]);
                float2 v3 = __half22float2(h[(size_t)s3 * 32 + lane]);
                accx = fmaf(x0, v0.x, accx); accy = fmaf(x0, v0.y, accy);
                accx = fmaf(x1, v1.x, accx); accy = fmaf(x1, v1.y, accy);
                accx = fmaf(x2, v2.x, accx); accy = fmaf(x2, v2.y, accy);
                accx = fmaf(x3, v3.x, accx); accy = fmaf(x3, v3.y, accy);
            }
            for (; k < cnt; k++) {
                float ex = __shfl_sync(FULL, ex_l, k);
                int   s  = __shfl_sync(FULL, s_l, k);
                float2 hv = __half22float2(h[(size_t)s * 32 + lane]);
                accx = fmaf(ex, hv.x, accx);
                accy = fmaf(ex, hv.y, accy);
            }
        }
    }
#pragma unroll
    for (int off = 16; off; off >>= 1) den += __shfl_xor_sync(FULL, den, off);
    den += exs;   // self-loop term (warp-uniform)
    float inv = 1.f / den;
    float2 o;
    o.x = elu_(accx * inv + bs[2 * lane + 0]);
    o.y = elu_(accy * inv + bs[2 * lane + 1]);
    *(float2*)(g_hx + (size_t)d * HH + 2 * lane) = o;
}

// ---------------- MLP head + pooled output, packed f32x2 FMA ----------------
__global__ __launch_bounds__(128) void final_kernel(
    const float* __restrict__ mw1, const float* __restrict__ mb1,
    const float* __restrict__ mw2, const float* __restrict__ mb2,
    const void* __restrict__ batch, float* __restrict__ out)
{
    __shared__ __align__(16) float mw1T[64 * 64];   // transposed: [j*64 + c]
    __shared__ __align__(16) float mw2s[64 * CC];
    __shared__ float mb1s[64], mb2s[CC];
    int tid = threadIdx.x;
    for (int i = tid; i < 64 * 64; i += 128) {
        int c = i >> 6, j = i & 63;
        mw1T[j * 64 + c] = mw1[i];
    }
    for (int i = tid; i < 64 * CC; i += 128) mw2s[i] = mw2[i];
    if (tid < 64) mb1s[tid] = mb1[tid];
    if (tid < CC) mb2s[tid] = mb2[tid];
    __syncthreads();

    int row = blockIdx.x * 128 + tid;
    int lane = tid & 31;
    bool active = row < NN;

    float o[CC];
#pragma unroll
    for (int c = 0; c < CC; c++) o[c] = 0.f;
    int g = 0;

    if (active) {
        size_t base = (size_t)row * HH;
        ull hf2[32];
        const ulonglong2* hp2 = (const ulonglong2*)(g_hx + base);
#pragma unroll
        for (int i = 0; i < 16; i++) {
            ulonglong2 p = hp2[i];
            hf2[2 * i + 0] = p.x;
            hf2[2 * i + 1] = p.y;
        }
        ull oc2[CC / 2];
#pragma unroll
        for (int c2 = 0; c2 < CC / 2; c2++) oc2[c2] = pack2(mb2s[2 * c2], mb2s[2 * c2 + 1]);

        const ulonglong2* m1 = (const ulonglong2*)mw1T;
#pragma unroll 4
        for (int j = 0; j < 64; j++) {
            ull t2 = pack2(mb1s[j], 0.f);
#pragma unroll
            for (int c4 = 0; c4 < 16; c4++) {
                ulonglong2 w = m1[j * 16 + c4];
                t2 = fma2(hf2[2 * c4 + 0], w.x, t2);
                t2 = fma2(hf2[2 * c4 + 1], w.y, t2);
            }
            float tlo, thi;
            unpack2(t2, tlo, thi);
            float t = fmaxf(tlo + thi, 0.f);
            ull tt = pack2(t, t);
            const ull* w2 = (const ull*)(mw2s + j * CC);
#pragma unroll
            for (int c2 = 0; c2 < CC / 2; c2++) oc2[c2] = fma2(tt, w2[c2], oc2[c2]);
        }
#pragma unroll
        for (int c2 = 0; c2 < CC / 2; c2++) unpack2(oc2[c2], o[2 * c2], o[2 * c2 + 1]);

        if (g_i64) g = (int)((const long long*)batch)[row];
        else       g = ((const int*)batch)[row];
    }

    unsigned mask = 0xffffffffu;
    int g0 = __shfl_sync(mask, g, 0);
    bool uni = __all_sync(mask, g == g0);
    if (uni) {
#pragma unroll
        for (int c = 0; c < CC; c++) {
            float v = o[c];
#pragma unroll
            for (int off = 16; off > 0; off >>= 1) v += __shfl_xor_sync(mask, v, off);
            if (lane == 0) atomicAdd(&out[g0 * CC + c], v);
        }
    } else {
        if (active) {
#pragma unroll
            for (int c = 0; c < CC; c++) atomicAdd(&out[g * CC + c], o[c]);
        }
    }
}

// ---------------- launch (single stream, 10 launches) ----------------
extern "C" void kernel_launch(void* const* d_in, const int* in_sizes, int n_in,
                              void* d_out, int out_size) {
    const float* x     = (const float*)d_in[0];
    const int*   ei_w  = (const int*)d_in[1];
    const void*  batch = d_in[2];
    const float* W1  = (const float*)d_in[3];
    const float* as1 = (const float*)d_in[4];
    const float* ad1 = (const float*)d_in[5];
    const float* b1  = (const float*)d_in[6];
    const float* W2  = (const float*)d_in[7];
    const float* as2 = (const float*)d_in[8];
    const float* ad2 = (const float*)d_in[9];
    const float* b2  = (const float*)d_in[10];
    const float* mw1 = (const float*)d_in[11];
    const float* mb1 = (const float*)d_in[12];
    const float* mw2 = (const float*)d_in[13];
    const float* mb2 = (const float*)d_in[14];
    float* out = (float*)d_out;

    int gb = (NN + 127) / 128;
    int nb = (NN + 255) / 256;
    int eb = (EE + 255) / 256;
    int wb = ((NN * 32) + 255) / 256;

    zero_kernel<<<nb, 256>>>(ei_w, out);
    prep_kernel<<<eb, 256>>>(ei_w);
    scan1_kernel<<<NB1, 1024>>>();
    scan3_kernel<<<nb, 256>>>();
    fill_kernel<<<eb, 256>>>(ei_w);

    gemm_gat<<<gb, 256>>>(0, x, W1, as1, ad1);
    gather_kernel<<<wb, 256>>>(b1);

    gemm_gat<<<gb, 256>>>(1, x, W2, as2, ad2);
    gather_kernel<<<wb, 256>>>(b2);

    final_kernel<<<gb, 128>>>(mw1, mb1, mw2, mb2, batch, out);
}